// round 15
// baseline (speedup 1.0000x reference)
#include <cuda_runtime.h>
#include <cuda_fp16.h>
#include <cstdint>

// Problem constants (fixed shapes per reference)
#define NNODES 50000
#define NEDGES 800000
#define DIMF   512
#define NGRAPH 64
#define NCLS   10
#define NB_SCAN ((NNODES + 1023) / 1024)   // 49
#define MTILES  ((NNODES + 127) / 128)     // 391

// ---------------- device scratch (no allocs allowed) ----------------
__device__ __half g_Xh[(size_t)NNODES * DIMF];   // layer1 Y output (renamed buffer)
__device__ __half g_Hh[(size_t)NNODES * DIMF];   // layer outputs fp16
__device__ __half g_Yh[(size_t)NNODES * DIMF];   // layer0 Y (gathered by spmm0)
__device__ __half g_Sh[(size_t)NNODES * DIMF];   // S (self term), per layer
__device__ __half g_Bh0[1024 * 512];             // [Wr0|Ws0]^T as [N=1024, K=512] fp16 K-major
__device__ __half g_Bh1[1024 * 512];             // [Wr1|Ws1]^T
__device__ int   g_cnt[NNODES];
__device__ int   g_cursor[NNODES];
__device__ int   g_rowptr[NNODES + 1];
__device__ int   g_col[NEDGES];
__device__ int   g_bsum[64];
__device__ int   g_boff[64];
__device__ int   g_goff[NGRAPH + 1];
__device__ float g_pooled[NGRAPH * DIMF];

// ---------------- low-level helpers ----------------
__device__ __forceinline__ uint32_t s2u(const void* p) {
    uint32_t a;
    asm("{ .reg .u64 t; cvta.to.shared.u64 t, %1; cvt.u32.u64 %0, t; }" : "=r"(a) : "l"(p));
    return a;
}
__device__ __forceinline__ void cp16(uint32_t d, const void* s) {
    asm volatile("cp.async.cg.shared.global [%0], [%1], 16;\n" :: "r"(d), "l"(s));
}
__device__ __forceinline__ void cp_commit() { asm volatile("cp.async.commit_group;\n" ::: "memory"); }
__device__ __forceinline__ void cp_wait1()  { asm volatile("cp.async.wait_group 1;\n" ::: "memory"); }
__device__ __forceinline__ void cp_wait0()  { asm volatile("cp.async.wait_group 0;\n" ::: "memory"); }

// fp16-accumulate HMMA
__device__ __forceinline__ void mma16816h(uint32_t* c, const uint32_t* a, const uint32_t* b) {
    asm volatile(
        "mma.sync.aligned.m16n8k16.row.col.f16.f16.f16.f16 "
        "{%0,%1},{%2,%3,%4,%5},{%6,%7},{%0,%1};"
        : "+r"(c[0]), "+r"(c[1])
        : "r"(a[0]), "r"(a[1]), "r"(a[2]), "r"(a[3]), "r"(b[0]), "r"(b[1]));
}
__device__ __forceinline__ void ldsm4(uint32_t* r, uint32_t a) {
    asm volatile("ldmatrix.sync.aligned.m8n8.x4.shared.b16 {%0,%1,%2,%3}, [%4];"
                 : "=r"(r[0]), "=r"(r[1]), "=r"(r[2]), "=r"(r[3]) : "r"(a));
}

// ---------------- setup kernels ----------------
__global__ void zero_buffers() {
    int i = blockIdx.x * 256 + threadIdx.x;
    if (i < NNODES) g_cnt[i] = 0;
    if (i < NGRAPH * DIMF) g_pooled[i] = 0.f;
}

__global__ void hist_edges(const int* __restrict__ ei) {
    int e = blockIdx.x * 256 + threadIdx.x;
    if (e < NEDGES) atomicAdd(&g_cnt[ei[NEDGES + e]], 1);
}

// hierarchical scan stage 1: per-1024-chunk sums
__global__ void scan_blocks() {
    __shared__ int ws[32];
    int t = threadIdx.x, b = blockIdx.x;
    long i = (long)b * 1024 + t;
    int v = (i < NNODES) ? g_cnt[i] : 0;
#pragma unroll
    for (int off = 16; off; off >>= 1) v += __shfl_down_sync(0xffffffffu, v, off);
    if ((t & 31) == 0) ws[t >> 5] = v;
    __syncthreads();
    if (t < 32) {
        int s = ws[t];
#pragma unroll
        for (int off = 16; off; off >>= 1) s += __shfl_down_sync(0xffffffffu, s, off);
        if (t == 0) g_bsum[b] = s;
    }
}

// stage 2: exclusive scan of 49 block sums
__global__ void scan_offsets() {
    __shared__ int sh[64];
    int t = threadIdx.x;
    int v = (t < NB_SCAN) ? g_bsum[t] : 0;
    sh[t] = v;
    __syncthreads();
    for (int off = 1; off < 64; off <<= 1) {
        int a = (t >= off) ? sh[t - off] : 0;
        __syncthreads();
        sh[t] += a;
        __syncthreads();
    }
    if (t < NB_SCAN) g_boff[t] = sh[t] - v;
}

// stage 3: local scan + global offset -> rowptr & cursor
__global__ void scan_write() {
    __shared__ int wsum[32];
    int t = threadIdx.x, b = blockIdx.x, lane = t & 31, w = t >> 5;
    long i = (long)b * 1024 + t;
    int v = (i < NNODES) ? g_cnt[i] : 0;
    int s = v;
#pragma unroll
    for (int off = 1; off < 32; off <<= 1) {
        int n = __shfl_up_sync(0xffffffffu, s, off);
        if (lane >= off) s += n;
    }
    if (lane == 31) wsum[w] = s;
    __syncthreads();
    if (w == 0) {
        int ws = wsum[lane];
#pragma unroll
        for (int off = 1; off < 32; off <<= 1) {
            int n = __shfl_up_sync(0xffffffffu, ws, off);
            if (lane >= off) ws += n;
        }
        wsum[lane] = ws;
    }
    __syncthreads();
    int base = g_boff[b] + ((w > 0) ? wsum[w - 1] : 0);
    if (i < NNODES) {
        g_rowptr[i + 1] = base + s;
        g_cursor[i]     = base + s - v;
    }
    if (b == 0 && t == 0) g_rowptr[0] = 0;
}

__global__ void scatter_edges(const int* __restrict__ ei) {
    int e = blockIdx.x * 256 + threadIdx.x;
    if (e < NEDGES) {
        int dst = ei[NEDGES + e];
        int src = ei[e];
        int pos = atomicAdd(&g_cursor[dst], 1);
        g_col[pos] = src;
    }
}

// batch is sorted -> graph offsets by binary search
__global__ void goff_search(const int* __restrict__ bat) {
    int g = threadIdx.x;
    if (g > NGRAPH) return;
    if (g == NGRAPH) { g_goff[g] = NNODES; return; }
    int lo = 0, hi = NNODES;
    while (lo < hi) {
        int mid = (lo + hi) >> 1;
        if (bat[mid] < g) lo = mid + 1; else hi = mid;
    }
    g_goff[g] = lo;
}

// ---------------- weight conversion ----------------
// Bt[n][k] = (n<512 ? Wr[k][n] : Ws[k][n-512]), fp16. grid (16,32), block (32,8)
__global__ void conv_w(const float* __restrict__ Wr, const float* __restrict__ Ws, int sel) {
    __shared__ float tile[32][33];
    __half* dst = sel ? g_Bh1 : g_Bh0;
    int k0 = blockIdx.x * 32, n0 = blockIdx.y * 32;
    const float* W = (n0 < 512) ? Wr : Ws;
    int ns0 = n0 & 511;
    int tx = threadIdx.x, ty = threadIdx.y;
#pragma unroll
    for (int j = 0; j < 4; j++)
        tile[ty + 8 * j][tx] = W[(long)(k0 + ty + 8 * j) * 512 + ns0 + tx];
    __syncthreads();
#pragma unroll
    for (int j = 0; j < 4; j++)
        dst[(long)(n0 + ty + 8 * j) * 512 + k0 + tx] = __float2half_rn(tile[tx][ty + 8 * j]);
}

// ---------------- fp16-accum mma.sync GEMM (R11 config; fused fp32-A convert) ----------------
// CTA tile BM=128 x BN=128, BK=32; 256 threads = 8 warps (2 M x 4 N), warp tile 64x32.
// AF32=1: A read as fp32 (x input), register-staged LDG one iteration ahead, converted
//         to fp16 during STS. AF32=0: A fp16 via cp.async (g_Hh).
#define SLD   40                       // smem row stride in halfs (32 data + 8 pad)
#define STG_B (128 * SLD * 2)          // 10240 B per A (or B) stage
#define STAGE_BYTES (2 * STG_B)        // 20480
#define GEMM_SMEM (3 * STAGE_BYTES)    // 61440
#define CLD 136                        // epilogue stage row stride in halfs

template<int AF32>
__global__ __launch_bounds__(256, 2)
void gemm_tc16(const float* __restrict__ Axf, int bSel, int ySel) {
    extern __shared__ __half dsm[];
    const uint32_t base = s2u(dsm);

    const __half* A16 = g_Hh;                 // fp16 A source (layer 1)
    const __half* Bt  = bSel ? g_Bh1 : g_Bh0;
    __half*       Yo  = ySel ? g_Xh : g_Yh;
    const int tid = threadIdx.x, wid = tid >> 5, lane = tid & 31;
    const int wm = (wid >> 2) * 64, wn = (wid & 3) * 32;
    const int grp = lane >> 2, tg = lane & 3;
    const long bm = (long)blockIdx.x * 128;
    const int  bn = blockIdx.y * 128;

    uint32_t acc[4][4][2];
#pragma unroll
    for (int mi = 0; mi < 4; mi++)
#pragma unroll
        for (int ni = 0; ni < 4; ni++) { acc[mi][ni][0] = 0u; acc[mi][ni][1] = 0u; }

    const uint32_t aOff = (uint32_t)(((wm + (lane & 15)) * SLD + (lane >> 4) * 8) * 2);
    const uint32_t bOff = (uint32_t)(((wn + (lane & 7) + ((lane >> 4) << 3)) * SLD +
                                      ((lane >> 3) & 1) * 8) * 2);

    // fp32-A register stage (AF32 path): 4 float4 per thread per k-tile
    float4 areg[4];
    const int aR  = tid >> 3;          // row within tile (+0,+32,+64,+96 by j)
    const int aF4 = (tid & 7) * 4;     // float offset within 32-float row

#define LDG_A32(kb)                                                                     \
    {                                                                                   \
        _Pragma("unroll")                                                               \
        for (int j = 0; j < 4; j++) {                                                   \
            long row = bm + aR + 32 * j;                                                \
            areg[j] = (row < NNODES) ? *(const float4*)(Axf + row * 512 + (kb) + aF4)   \
                                     : make_float4(0.f, 0.f, 0.f, 0.f);                 \
        }                                                                               \
    }
#define STS_A32(s)                                                                      \
    {                                                                                   \
        uint32_t ab = base + (uint32_t)(s) * STAGE_BYTES;                               \
        _Pragma("unroll")                                                               \
        for (int j = 0; j < 4; j++) {                                                   \
            __half2 h0 = __floats2half2_rn(areg[j].x, areg[j].y);                       \
            __half2 h1 = __floats2half2_rn(areg[j].z, areg[j].w);                       \
            uint2 u;                                                                    \
            u.x = *(uint32_t*)&h0;                                                      \
            u.y = *(uint32_t*)&h1;                                                      \
            *(uint2*)((char*)dsm + ab - base + ((aR + 32 * j) * SLD + aF4) * 2) = u;    \
        }                                                                               \
    }
#define CP_B(s, kb)                                                                     \
    {                                                                                   \
        uint32_t bb = base + (uint32_t)(s) * STAGE_BYTES + STG_B;                       \
        _Pragma("unroll")                                                               \
        for (int j = 0; j < 2; j++) {                                                   \
            int c  = tid + 256 * j;                                                     \
            int r  = c >> 2;                                                            \
            int c8 = (c & 3) * 8;                                                       \
            cp16(bb + (uint32_t)(r * SLD + c8) * 2, Bt + (long)(bn + r) * 512 + (kb) + c8); \
        }                                                                               \
        cp_commit();                                                                    \
    }
#define LOAD_STAGE16(s, kb)                                                             \
    {                                                                                   \
        uint32_t ab = base + (uint32_t)(s) * STAGE_BYTES;                               \
        uint32_t bb = ab + STG_B;                                                       \
        _Pragma("unroll")                                                               \
        for (int j = 0; j < 2; j++) {                                                   \
            int c  = tid + 256 * j;                                                     \
            int r  = c >> 2;                                                            \
            int c8 = (c & 3) * 8;                                                       \
            long row = bm + r;                                                          \
            if (row < NNODES)                                                           \
                cp16(ab + (uint32_t)(r * SLD + c8) * 2, A16 + row * 512 + (kb) + c8);   \
            cp16(bb + (uint32_t)(r * SLD + c8) * 2, Bt + (long)(bn + r) * 512 + (kb) + c8); \
        }                                                                               \
        cp_commit();                                                                    \
    }

    // prologue
    if (AF32) {
        LDG_A32(0);
        STS_A32(0);        // stage 0 A in smem (stalls once on LDG; prologue only)
        LDG_A32(32);       // stage 1 A in regs; STS at kt=0
        CP_B(0, 0);
        CP_B(1, 32);
    } else {
        LOAD_STAGE16(0, 0);
        LOAD_STAGE16(1, 32);
    }

    int stage = 0;
    for (int kt = 0; kt < 16; kt++) {
        if (kt == 15) cp_wait0(); else cp_wait1();
        __syncthreads();
        if (AF32) {
            if (kt + 1 < 16) {
                int s1 = stage + 1; if (s1 >= 3) s1 -= 3;
                STS_A32(s1);                        // A(kt+1) regs -> smem
            }
            if (kt + 2 < 16) {
                int s2 = stage + 2; if (s2 >= 3) s2 -= 3;
                LDG_A32((kt + 2) * 32);             // A(kt+2) -> regs (latency hidden by mma)
                CP_B(s2, (kt + 2) * 32);
            }
        } else {
            if (kt + 2 < 16) {
                int s2 = stage + 2; if (s2 >= 3) s2 -= 3;
                LOAD_STAGE16(s2, (kt + 2) * 32);
            }
        }

        const uint32_t sb = base + (uint32_t)stage * STAGE_BYTES;
        const uint32_t aLd = sb + aOff, bLd = sb + STG_B + bOff;
#pragma unroll
        for (int ks = 0; ks < 2; ks++) {
            uint32_t af[4][4], bq[2][4];
#pragma unroll
            for (int mi = 0; mi < 4; mi++)
                ldsm4(af[mi], aLd + (uint32_t)(mi * 16 * SLD * 2 + ks * 32));
#pragma unroll
            for (int nj = 0; nj < 2; nj++)
                ldsm4(bq[nj], bLd + (uint32_t)(nj * 16 * SLD * 2 + ks * 32));
#pragma unroll
            for (int mi = 0; mi < 4; mi++)
#pragma unroll
                for (int ni = 0; ni < 4; ni++)
                    mma16816h(acc[mi][ni], af[mi], &bq[ni >> 1][(ni & 1) * 2]);
        }
        if (++stage >= 3) stage -= 3;
    }

    // ---------------- staged epilogue (acc already fp16) ----------------
    __syncthreads();
#pragma unroll
    for (int mi = 0; mi < 4; mi++) {
#pragma unroll
        for (int ni = 0; ni < 4; ni++) {
            int r = wm + mi * 16 + grp;
            int c = wn + ni * 8 + tg * 2;
            *(uint32_t*)(dsm + r * CLD + c)       = acc[mi][ni][0];
            *(uint32_t*)(dsm + (r + 8) * CLD + c) = acc[mi][ni][1];
        }
    }
    __syncthreads();
    {
        int r  = tid >> 1;
        int hb = (tid & 1) * 64;
        long grow = bm + r;
        if (grow < NNODES) {
            int gcol = bn + hb;
            __half* bp = (gcol < 512) ? (Yo + grow * 512 + gcol)
                                      : (g_Sh + grow * 512 + (gcol - 512));
            const uint4* src = (const uint4*)(dsm + r * CLD + hb);
#pragma unroll
            for (int q = 0; q < 8; q++) ((uint4*)bp)[q] = src[q];
        }
    }
#undef LDG_A32
#undef STS_A32
#undef CP_B
#undef LOAD_STAGE16
}

// ---------------- SpMM: Hh[i] = relu( Sh[i] + br + sum_{j in N(i)} Y[j] ) ----------------
__global__ void spmm_f16(const float* __restrict__ br, int ySel) {
    const __half* Y = ySel ? g_Xh : g_Yh;
    int i = blockIdx.x;
    int t = threadIdx.x;   // 128 threads x 4 features
    int s = g_rowptr[i], e = g_rowptr[i + 1];

    uint2 su = *(const uint2*)(g_Sh + (long)i * 512 + t * 4);
    float2 s0 = __half22float2(*(__half2*)&su.x), s1 = __half22float2(*(__half2*)&su.y);
    float4 b = *(const float4*)(br + t * 4);
    float4 acc = make_float4(s0.x + b.x, s0.y + b.y, s1.x + b.z, s1.y + b.w);

    int p = s;
    for (; p + 1 < e; p += 2) {
        int j0 = __ldg(&g_col[p]);
        int j1 = __ldg(&g_col[p + 1]);
        uint2 u0 = *(const uint2*)(Y + (long)j0 * 512 + t * 4);
        uint2 u1 = *(const uint2*)(Y + (long)j1 * 512 + t * 4);
        float2 a0 = __half22float2(*(__half2*)&u0.x), a1 = __half22float2(*(__half2*)&u0.y);
        float2 c0 = __half22float2(*(__half2*)&u1.x), c1 = __half22float2(*(__half2*)&u1.y);
        acc.x += a0.x + c0.x; acc.y += a0.y + c0.y;
        acc.z += a1.x + c1.x; acc.w += a1.y + c1.y;
    }
    if (p < e) {
        int j = __ldg(&g_col[p]);
        uint2 u = *(const uint2*)(Y + (long)j * 512 + t * 4);
        float2 f0 = __half22float2(*(__half2*)&u.x), f1 = __half22float2(*(__half2*)&u.y);
        acc.x += f0.x; acc.y += f0.y; acc.z += f1.x; acc.w += f1.y;
    }
    acc.x = fmaxf(acc.x, 0.f);
    acc.y = fmaxf(acc.y, 0.f);
    acc.z = fmaxf(acc.z, 0.f);
    acc.w = fmaxf(acc.w, 0.f);

    __half2 o0 = __floats2half2_rn(acc.x, acc.y);
    __half2 o1 = __floats2half2_rn(acc.z, acc.w);
    uint2 st;
    st.x = *(uint32_t*)&o0;
    st.y = *(uint32_t*)&o1;
    *(uint2*)(g_Hh + (long)i * 512 + t * 4) = st;
}

// ---------------- pooling + classifier ----------------
__global__ void pool_partial() {
    int g = blockIdx.x, ch = blockIdx.y;
    int t = threadIdx.x;   // 128
    int s = g_goff[g], e = g_goff[g + 1];
    float4 acc = make_float4(0.f, 0.f, 0.f, 0.f);
    for (int n = s + ch; n < e; n += gridDim.y) {
        uint2 u = *(const uint2*)(g_Hh + (long)n * 512 + t * 4);
        float2 f0 = __half22float2(*(__half2*)&u.x), f1 = __half22float2(*(__half2*)&u.y);
        acc.x += f0.x; acc.y += f0.y; acc.z += f1.x; acc.w += f1.y;
    }
    float* dst = &g_pooled[g * 512 + t * 4];
    atomicAdd(dst + 0, acc.x);
    atomicAdd(dst + 1, acc.y);
    atomicAdd(dst + 2, acc.z);
    atomicAdd(dst + 3, acc.w);
}

// fused: mean + relu + linear
__global__ void final_linear(const float* __restrict__ Wl, const float* __restrict__ bl,
                             float* __restrict__ out) {
    __shared__ float sh[512];
    int g = blockIdx.x, t = threadIdx.x;   // 320 threads
    int cnt = g_goff[g + 1] - g_goff[g];
    float inv = 1.f / (float)(cnt > 0 ? cnt : 1);
    for (int f = t; f < 512; f += blockDim.x) {
        float v = g_pooled[g * 512 + f] * inv;
        sh[f] = v > 0.f ? v : 0.f;
    }
    __syncthreads();
    int w = t >> 5, lane = t & 31;
    if (w < NCLS) {
        float s = 0.f;
        for (int f = lane; f < 512; f += 32) s += sh[f] * Wl[f * NCLS + w];
#pragma unroll
        for (int o = 16; o; o >>= 1) s += __shfl_down_sync(0xffffffffu, s, o);
        if (lane == 0) out[g * NCLS + w] = s + bl[w];
    }
}

// ---------------- launch ----------------
extern "C" void kernel_launch(void* const* d_in, const int* in_sizes, int n_in,
                              void* d_out, int out_size) {
    const float* x   = (const float*)d_in[0];
    const int*   ei  = (const int*)d_in[1];
    const int*   bat = (const int*)d_in[2];
    const float* Wr0 = (const float*)d_in[3];
    const float* br0 = (const float*)d_in[4];
    const float* Ws0 = (const float*)d_in[5];
    const float* Wr1 = (const float*)d_in[6];
    const float* br1 = (const float*)d_in[7];
    const float* Ws1 = (const float*)d_in[8];
    const float* Wl  = (const float*)d_in[9];
    const float* bl  = (const float*)d_in[10];
    float* out = (float*)d_out;

    static cudaStream_t s1 = nullptr;
    static cudaEvent_t  e0 = nullptr, e1 = nullptr;
    if (!s1) {
        cudaStreamCreateWithFlags(&s1, cudaStreamNonBlocking);
        cudaEventCreateWithFlags(&e0, cudaEventDisableTiming);
        cudaEventCreateWithFlags(&e1, cudaEventDisableTiming);
        cudaFuncSetAttribute(gemm_tc16<1>, cudaFuncAttributeMaxDynamicSharedMemorySize, GEMM_SMEM);
        cudaFuncSetAttribute(gemm_tc16<0>, cudaFuncAttributeMaxDynamicSharedMemorySize, GEMM_SMEM);
    }

    const int NBLK = (NNODES + 255) / 256;
    const int EBLK = (NEDGES + 255) / 256;
    dim3 ggrid(MTILES, 8);   // 391 M-tiles x 8 N-tiles(128) over N=1024

    // fork side stream at entry (CSR chain + conv_w1 run concurrently with gemm0)
    cudaEventRecord(e0, 0);
    cudaStreamWaitEvent(s1, e0, 0);

    // main stream: conv_w0 then gemm0 (A-conversion fused into gemm0)
    conv_w<<<dim3(16, 32), dim3(32, 8)>>>(Wr0, Ws0, 0);
    gemm_tc16<1><<<ggrid, 256, GEMM_SMEM>>>(x, 0, 0);   // A=x(fp32), B=W0, Y->g_Yh

    // side stream: CSR + batch structure + conv_w1
    zero_buffers<<<NBLK, 256, 0, s1>>>();
    hist_edges<<<EBLK, 256, 0, s1>>>(ei);
    scan_blocks<<<NB_SCAN, 1024, 0, s1>>>();
    scan_offsets<<<1, 64, 0, s1>>>();
    scan_write<<<NB_SCAN, 1024, 0, s1>>>();
    scatter_edges<<<EBLK, 256, 0, s1>>>(ei);
    goff_search<<<1, 128, 0, s1>>>(bat);
    conv_w<<<dim3(16, 32), dim3(32, 8), 0, s1>>>(Wr1, Ws1, 1);
    cudaEventRecord(e1, s1);

    // join: spmm needs CSR (and gemm1 needs conv_w1, ordered behind this wait)
    cudaStreamWaitEvent(0, e1, 0);
    spmm_f16<<<NNODES, 128>>>(br0, 0);

    // layer 1 (serial — chunked overlap measured as a regression in R13)
    gemm_tc16<0><<<ggrid, 256, GEMM_SMEM>>>(nullptr, 1, 1);   // A=g_Hh, B=W1, Y->g_Xh
    spmm_f16<<<NNODES, 128>>>(br1, 1);

    // pool + classify
    pool_partial<<<dim3(NGRAPH, 16), 128>>>();
    final_linear<<<NGRAPH, 320>>>(Wl, bl, out);
}

// round 16
// speedup vs baseline: 1.0357x; 1.0357x over previous
#include <cuda_runtime.h>
#include <cuda_fp16.h>
#include <cstdint>

// Problem constants (fixed shapes per reference)
#define NNODES 50000
#define NEDGES 800000
#define DIMF   512
#define NGRAPH 64
#define NCLS   10
#define NB_SCAN ((NNODES + 1023) / 1024)   // 49
#define MTILES  ((NNODES + 127) / 128)     // 391

// ---------------- device scratch (no allocs allowed) ----------------
__device__ __half g_Xh[(size_t)NNODES * DIMF];   // x fp16 (layer0 A); reused as layer1 Y
__device__ __half g_Hh[(size_t)NNODES * DIMF];   // layer outputs fp16
__device__ __half g_Yh[(size_t)NNODES * DIMF];   // layer0 Y (gathered by spmm0)
__device__ __half g_Sh[(size_t)NNODES * DIMF];   // S (self term), per layer
__device__ __half g_Bh0[1024 * 512];             // [Wr0|Ws0]^T as [N=1024, K=512] fp16 K-major
__device__ __half g_Bh1[1024 * 512];             // [Wr1|Ws1]^T
__device__ int   g_cnt[NNODES];
__device__ int   g_cursor[NNODES];
__device__ int   g_rowptr[NNODES + 1];
__device__ int   g_col[NEDGES];
__device__ int   g_bsum[64];
__device__ int   g_boff[64];
__device__ int   g_goff[NGRAPH + 1];
__device__ float g_pooled[NGRAPH * DIMF];

// ---------------- low-level helpers ----------------
__device__ __forceinline__ uint32_t s2u(const void* p) {
    uint32_t a;
    asm("{ .reg .u64 t; cvta.to.shared.u64 t, %1; cvt.u32.u64 %0, t; }" : "=r"(a) : "l"(p));
    return a;
}
__device__ __forceinline__ void cp16(uint32_t d, const void* s) {
    asm volatile("cp.async.cg.shared.global [%0], [%1], 16;\n" :: "r"(d), "l"(s));
}
__device__ __forceinline__ void cp_commit() { asm volatile("cp.async.commit_group;\n" ::: "memory"); }
__device__ __forceinline__ void cp_wait1()  { asm volatile("cp.async.wait_group 1;\n" ::: "memory"); }
__device__ __forceinline__ void cp_wait0()  { asm volatile("cp.async.wait_group 0;\n" ::: "memory"); }

// fp16-accumulate HMMA
__device__ __forceinline__ void mma16816h(uint32_t* c, const uint32_t* a, const uint32_t* b) {
    asm volatile(
        "mma.sync.aligned.m16n8k16.row.col.f16.f16.f16.f16 "
        "{%0,%1},{%2,%3,%4,%5},{%6,%7},{%0,%1};"
        : "+r"(c[0]), "+r"(c[1])
        : "r"(a[0]), "r"(a[1]), "r"(a[2]), "r"(a[3]), "r"(b[0]), "r"(b[1]));
}
__device__ __forceinline__ void ldsm4(uint32_t* r, uint32_t a) {
    asm volatile("ldmatrix.sync.aligned.m8n8.x4.shared.b16 {%0,%1,%2,%3}, [%4];"
                 : "=r"(r[0]), "=r"(r[1]), "=r"(r[2]), "=r"(r[3]) : "r"(a));
}

// ---------------- setup kernels ----------------
__global__ void zero_buffers() {
    int i = blockIdx.x * 256 + threadIdx.x;
    if (i < NNODES) g_cnt[i] = 0;
    if (i < NGRAPH * DIMF) g_pooled[i] = 0.f;
}

__global__ void hist_edges(const int* __restrict__ ei) {
    int e = blockIdx.x * 256 + threadIdx.x;
    if (e < NEDGES) atomicAdd(&g_cnt[ei[NEDGES + e]], 1);
}

// hierarchical scan stage 1: per-1024-chunk sums
__global__ void scan_blocks() {
    __shared__ int ws[32];
    int t = threadIdx.x, b = blockIdx.x;
    long i = (long)b * 1024 + t;
    int v = (i < NNODES) ? g_cnt[i] : 0;
#pragma unroll
    for (int off = 16; off; off >>= 1) v += __shfl_down_sync(0xffffffffu, v, off);
    if ((t & 31) == 0) ws[t >> 5] = v;
    __syncthreads();
    if (t < 32) {
        int s = ws[t];
#pragma unroll
        for (int off = 16; off; off >>= 1) s += __shfl_down_sync(0xffffffffu, s, off);
        if (t == 0) g_bsum[b] = s;
    }
}

// stage 2: exclusive scan of 49 block sums
__global__ void scan_offsets() {
    __shared__ int sh[64];
    int t = threadIdx.x;
    int v = (t < NB_SCAN) ? g_bsum[t] : 0;
    sh[t] = v;
    __syncthreads();
    for (int off = 1; off < 64; off <<= 1) {
        int a = (t >= off) ? sh[t - off] : 0;
        __syncthreads();
        sh[t] += a;
        __syncthreads();
    }
    if (t < NB_SCAN) g_boff[t] = sh[t] - v;
}

// stage 3: local scan + global offset -> rowptr & cursor
__global__ void scan_write() {
    __shared__ int wsum[32];
    int t = threadIdx.x, b = blockIdx.x, lane = t & 31, w = t >> 5;
    long i = (long)b * 1024 + t;
    int v = (i < NNODES) ? g_cnt[i] : 0;
    int s = v;
#pragma unroll
    for (int off = 1; off < 32; off <<= 1) {
        int n = __shfl_up_sync(0xffffffffu, s, off);
        if (lane >= off) s += n;
    }
    if (lane == 31) wsum[w] = s;
    __syncthreads();
    if (w == 0) {
        int ws = wsum[lane];
#pragma unroll
        for (int off = 1; off < 32; off <<= 1) {
            int n = __shfl_up_sync(0xffffffffu, ws, off);
            if (lane >= off) ws += n;
        }
        wsum[lane] = ws;
    }
    __syncthreads();
    int base = g_boff[b] + ((w > 0) ? wsum[w - 1] : 0);
    if (i < NNODES) {
        g_rowptr[i + 1] = base + s;
        g_cursor[i]     = base + s - v;
    }
    if (b == 0 && t == 0) g_rowptr[0] = 0;
}

__global__ void scatter_edges(const int* __restrict__ ei) {
    int e = blockIdx.x * 256 + threadIdx.x;
    if (e < NEDGES) {
        int dst = ei[NEDGES + e];
        int src = ei[e];
        int pos = atomicAdd(&g_cursor[dst], 1);
        g_col[pos] = src;
    }
}

// batch is sorted -> graph offsets by binary search
__global__ void goff_search(const int* __restrict__ bat) {
    int g = threadIdx.x;
    if (g > NGRAPH) return;
    if (g == NGRAPH) { g_goff[g] = NNODES; return; }
    int lo = 0, hi = NNODES;
    while (lo < hi) {
        int mid = (lo + hi) >> 1;
        if (bat[mid] < g) lo = mid + 1; else hi = mid;
    }
    g_goff[g] = lo;
}

// ---------------- conversion kernels ----------------
__global__ void conv_x(const float* __restrict__ x) {
    long i = (long)blockIdx.x * 256 + threadIdx.x;   // float4 index
    if (i < (long)NNODES * DIMF / 4) {
        float4 v = ((const float4*)x)[i];
        __half2 a = __floats2half2_rn(v.x, v.y);
        __half2 b = __floats2half2_rn(v.z, v.w);
        uint2 u;
        u.x = *(uint32_t*)&a;
        u.y = *(uint32_t*)&b;
        ((uint2*)g_Xh)[i] = u;
    }
}

// Bt[n][k] = (n<512 ? Wr[k][n] : Ws[k][n-512]), fp16. grid (16,32), block (32,8)
__global__ void conv_w(const float* __restrict__ Wr, const float* __restrict__ Ws, int sel) {
    __shared__ float tile[32][33];
    __half* dst = sel ? g_Bh1 : g_Bh0;
    int k0 = blockIdx.x * 32, n0 = blockIdx.y * 32;
    const float* W = (n0 < 512) ? Wr : Ws;
    int ns0 = n0 & 511;
    int tx = threadIdx.x, ty = threadIdx.y;
#pragma unroll
    for (int j = 0; j < 4; j++)
        tile[ty + 8 * j][tx] = W[(long)(k0 + ty + 8 * j) * 512 + ns0 + tx];
    __syncthreads();
#pragma unroll
    for (int j = 0; j < 4; j++)
        dst[(long)(n0 + ty + 8 * j) * 512 + k0 + tx] = __float2half_rn(tile[tx][ty + 8 * j]);
}

// ---------------- fp16-accum mma.sync GEMM (R11 measured-best config) ----------------
// CTA tile BM=128 x BN=128, BK=32; 256 threads = 8 warps (2 M x 4 N), warp tile 64x32.
// fp16 accumulators -> ~80 regs -> 3 CTAs/SM. 3-stage cp.async; staged smem epilogue.
#define SLD   40                       // smem row stride in halfs (32 data + 8 pad)
#define STG_B (128 * SLD * 2)          // 10240 B per A (or B) stage
#define STAGE_BYTES (2 * STG_B)        // 20480
#define GEMM_SMEM (3 * STAGE_BYTES)    // 61440
#define CLD 136                        // epilogue stage row stride in halfs

__global__ __launch_bounds__(256, 3)
void gemm_tc16(int aSel, int bSel, int ySel) {
    extern __shared__ __half dsm[];
    const uint32_t base = s2u(dsm);

    const __half* A  = aSel ? g_Hh : g_Xh;
    const __half* Bt = bSel ? g_Bh1 : g_Bh0;
    __half*       Yo = ySel ? g_Xh : g_Yh;
    const int tid = threadIdx.x, wid = tid >> 5, lane = tid & 31;
    const int wm = (wid >> 2) * 64, wn = (wid & 3) * 32;
    const int grp = lane >> 2, tg = lane & 3;
    const long bm = (long)blockIdx.x * 128;
    const int  bn = blockIdx.y * 128;

    uint32_t acc[4][4][2];
#pragma unroll
    for (int mi = 0; mi < 4; mi++)
#pragma unroll
        for (int ni = 0; ni < 4; ni++) { acc[mi][ni][0] = 0u; acc[mi][ni][1] = 0u; }

    const uint32_t aOff = (uint32_t)(((wm + (lane & 15)) * SLD + (lane >> 4) * 8) * 2);
    const uint32_t bOff = (uint32_t)(((wn + (lane & 7) + ((lane >> 4) << 3)) * SLD +
                                      ((lane >> 3) & 1) * 8) * 2);

#define LOAD_STAGE(s, kb)                                                                \
    {                                                                                    \
        uint32_t ab = base + (uint32_t)(s) * STAGE_BYTES;                                \
        uint32_t bb = ab + STG_B;                                                        \
        _Pragma("unroll")                                                                \
        for (int j = 0; j < 2; j++) {                                                    \
            int c  = tid + 256 * j;                                                      \
            int r  = c >> 2;                                                             \
            int c8 = (c & 3) * 8;                                                        \
            long row = bm + r;                                                           \
            if (row < NNODES)                                                            \
                cp16(ab + (uint32_t)(r * SLD + c8) * 2, A + row * 512 + (kb) + c8);      \
            cp16(bb + (uint32_t)(r * SLD + c8) * 2, Bt + (long)(bn + r) * 512 + (kb) + c8); \
        }                                                                                \
        cp_commit();                                                                     \
    }

    LOAD_STAGE(0, 0);
    LOAD_STAGE(1, 32);

    int stage = 0;
    for (int kt = 0; kt < 16; kt++) {
        if (kt == 15) cp_wait0(); else cp_wait1();
        __syncthreads();
        if (kt + 2 < 16) {
            int ns = stage + 2; if (ns >= 3) ns -= 3;
            LOAD_STAGE(ns, (kt + 2) * 32);
        }

        const uint32_t sb = base + (uint32_t)stage * STAGE_BYTES;
        const uint32_t aLd = sb + aOff, bLd = sb + STG_B + bOff;
#pragma unroll
        for (int ks = 0; ks < 2; ks++) {
            uint32_t af[4][4], bq[2][4];
#pragma unroll
            for (int mi = 0; mi < 4; mi++)
                ldsm4(af[mi], aLd + (uint32_t)(mi * 16 * SLD * 2 + ks * 32));
#pragma unroll
            for (int nj = 0; nj < 2; nj++)
                ldsm4(bq[nj], bLd + (uint32_t)(nj * 16 * SLD * 2 + ks * 32));
#pragma unroll
            for (int mi = 0; mi < 4; mi++)
#pragma unroll
                for (int ni = 0; ni < 4; ni++)
                    mma16816h(acc[mi][ni], af[mi], &bq[ni >> 1][(ni & 1) * 2]);
        }
        if (++stage >= 3) stage -= 3;
    }

    // ---------------- staged epilogue (acc already fp16) ----------------
    __syncthreads();
#pragma unroll
    for (int mi = 0; mi < 4; mi++) {
#pragma unroll
        for (int ni = 0; ni < 4; ni++) {
            int r = wm + mi * 16 + grp;
            int c = wn + ni * 8 + tg * 2;
            *(uint32_t*)(dsm + r * CLD + c)       = acc[mi][ni][0];
            *(uint32_t*)(dsm + (r + 8) * CLD + c) = acc[mi][ni][1];
        }
    }
    __syncthreads();
    {
        int r  = tid >> 1;
        int hb = (tid & 1) * 64;
        long grow = bm + r;
        if (grow < NNODES) {
            int gcol = bn + hb;
            __half* bp = (gcol < 512) ? (Yo + grow * 512 + gcol)
                                      : (g_Sh + grow * 512 + (gcol - 512));
            const uint4* src = (const uint4*)(dsm + r * CLD + hb);
#pragma unroll
            for (int q = 0; q < 8; q++) ((uint4*)bp)[q] = src[q];
        }
    }
#undef LOAD_STAGE
}

// ---------------- SpMM: Hh[i] = relu( Sh[i] + br + sum_{j in N(i)} Y[j] ) ----------------
__global__ void spmm_f16(const float* __restrict__ br, int ySel) {
    const __half* Y = ySel ? g_Xh : g_Yh;
    int i = blockIdx.x;
    int t = threadIdx.x;   // 128 threads x 4 features
    int s = g_rowptr[i], e = g_rowptr[i + 1];

    uint2 su = *(const uint2*)(g_Sh + (long)i * 512 + t * 4);
    float2 s0 = __half22float2(*(__half2*)&su.x), s1 = __half22float2(*(__half2*)&su.y);
    float4 b = *(const float4*)(br + t * 4);
    float4 acc = make_float4(s0.x + b.x, s0.y + b.y, s1.x + b.z, s1.y + b.w);

    int p = s;
    for (; p + 1 < e; p += 2) {
        int j0 = __ldg(&g_col[p]);
        int j1 = __ldg(&g_col[p + 1]);
        uint2 u0 = *(const uint2*)(Y + (long)j0 * 512 + t * 4);
        uint2 u1 = *(const uint2*)(Y + (long)j1 * 512 + t * 4);
        float2 a0 = __half22float2(*(__half2*)&u0.x), a1 = __half22float2(*(__half2*)&u0.y);
        float2 c0 = __half22float2(*(__half2*)&u1.x), c1 = __half22float2(*(__half2*)&u1.y);
        acc.x += a0.x + c0.x; acc.y += a0.y + c0.y;
        acc.z += a1.x + c1.x; acc.w += a1.y + c1.y;
    }
    if (p < e) {
        int j = __ldg(&g_col[p]);
        uint2 u = *(const uint2*)(Y + (long)j * 512 + t * 4);
        float2 f0 = __half22float2(*(__half2*)&u.x), f1 = __half22float2(*(__half2*)&u.y);
        acc.x += f0.x; acc.y += f0.y; acc.z += f1.x; acc.w += f1.y;
    }
    acc.x = fmaxf(acc.x, 0.f);
    acc.y = fmaxf(acc.y, 0.f);
    acc.z = fmaxf(acc.z, 0.f);
    acc.w = fmaxf(acc.w, 0.f);

    __half2 o0 = __floats2half2_rn(acc.x, acc.y);
    __half2 o1 = __floats2half2_rn(acc.z, acc.w);
    uint2 st;
    st.x = *(uint32_t*)&o0;
    st.y = *(uint32_t*)&o1;
    *(uint2*)(g_Hh + (long)i * 512 + t * 4) = st;
}

// ---------------- pooling + classifier ----------------
__global__ void pool_partial() {
    int g = blockIdx.x, ch = blockIdx.y;
    int t = threadIdx.x;   // 128
    int s = g_goff[g], e = g_goff[g + 1];
    float4 acc = make_float4(0.f, 0.f, 0.f, 0.f);
    for (int n = s + ch; n < e; n += gridDim.y) {
        uint2 u = *(const uint2*)(g_Hh + (long)n * 512 + t * 4);
        float2 f0 = __half22float2(*(__half2*)&u.x), f1 = __half22float2(*(__half2*)&u.y);
        acc.x += f0.x; acc.y += f0.y; acc.z += f1.x; acc.w += f1.y;
    }
    float* dst = &g_pooled[g * 512 + t * 4];
    atomicAdd(dst + 0, acc.x);
    atomicAdd(dst + 1, acc.y);
    atomicAdd(dst + 2, acc.z);
    atomicAdd(dst + 3, acc.w);
}

// fused: mean + relu + linear
__global__ void final_linear(const float* __restrict__ Wl, const float* __restrict__ bl,
                             float* __restrict__ out) {
    __shared__ float sh[512];
    int g = blockIdx.x, t = threadIdx.x;   // 320 threads
    int cnt = g_goff[g + 1] - g_goff[g];
    float inv = 1.f / (float)(cnt > 0 ? cnt : 1);
    for (int f = t; f < 512; f += blockDim.x) {
        float v = g_pooled[g * 512 + f] * inv;
        sh[f] = v > 0.f ? v : 0.f;
    }
    __syncthreads();
    int w = t >> 5, lane = t & 31;
    if (w < NCLS) {
        float s = 0.f;
        for (int f = lane; f < 512; f += 32) s += sh[f] * Wl[f * NCLS + w];
#pragma unroll
        for (int o = 16; o; o >>= 1) s += __shfl_down_sync(0xffffffffu, s, o);
        if (lane == 0) out[g * NCLS + w] = s + bl[w];
    }
}

// ---------------- launch ----------------
extern "C" void kernel_launch(void* const* d_in, const int* in_sizes, int n_in,
                              void* d_out, int out_size) {
    const float* x   = (const float*)d_in[0];
    const int*   ei  = (const int*)d_in[1];
    const int*   bat = (const int*)d_in[2];
    const float* Wr0 = (const float*)d_in[3];
    const float* br0 = (const float*)d_in[4];
    const float* Ws0 = (const float*)d_in[5];
    const float* Wr1 = (const float*)d_in[6];
    const float* br1 = (const float*)d_in[7];
    const float* Ws1 = (const float*)d_in[8];
    const float* Wl  = (const float*)d_in[9];
    const float* bl  = (const float*)d_in[10];
    float* out = (float*)d_out;

    static cudaStream_t s1 = nullptr;
    static cudaEvent_t  e0 = nullptr, e1 = nullptr;
    if (!s1) {
        cudaStreamCreateWithFlags(&s1, cudaStreamNonBlocking);
        cudaEventCreateWithFlags(&e0, cudaEventDisableTiming);
        cudaEventCreateWithFlags(&e1, cudaEventDisableTiming);
        cudaFuncSetAttribute(gemm_tc16, cudaFuncAttributeMaxDynamicSharedMemorySize, GEMM_SMEM);
    }

    const int NBLK = (NNODES + 255) / 256;
    const int EBLK = (NEDGES + 255) / 256;
    dim3 ggrid(MTILES, 8);   // 391 M-tiles x 8 N-tiles(128) over N=1024

    // fork side stream at entry (CSR chain + conv_w1 run concurrently with conv+gemm0)
    cudaEventRecord(e0, 0);
    cudaStreamWaitEvent(s1, e0, 0);

    // main stream: conv_x(1), conv_w0(2), gemm0(3)
    conv_x<<<(NNODES * DIMF / 4 + 255) / 256, 256>>>(x);
    conv_w<<<dim3(16, 32), dim3(32, 8)>>>(Wr0, Ws0, 0);
    gemm_tc16<<<ggrid, 256, GEMM_SMEM>>>(0, 0, 0);   // A=Xh, B=W0, Y->g_Yh

    // side stream: CSR + batch structure + conv_w1
    zero_buffers<<<NBLK, 256, 0, s1>>>();
    hist_edges<<<EBLK, 256, 0, s1>>>(ei);
    scan_blocks<<<NB_SCAN, 1024, 0, s1>>>();
    scan_offsets<<<1, 64, 0, s1>>>();
    scan_write<<<NB_SCAN, 1024, 0, s1>>>();
    scatter_edges<<<EBLK, 256, 0, s1>>>(ei);
    goff_search<<<1, 128, 0, s1>>>(bat);
    conv_w<<<dim3(16, 32), dim3(32, 8), 0, s1>>>(Wr1, Ws1, 1);
    cudaEventRecord(e1, s1);

    // join: spmm needs CSR; gemm1 (behind it) needs conv_w1
    cudaStreamWaitEvent(0, e1, 0);
    spmm_f16<<<NNODES, 128>>>(br0, 0);

    // layer 1 (serial — chunked overlap measured as a regression in R13)
    gemm_tc16<<<ggrid, 256, GEMM_SMEM>>>(1, 1, 1);   // A=Hh, B=W1, Y->g_Xh
    spmm_f16<<<NNODES, 128>>>(br1, 1);

    // pool + classify
    pool_partial<<<dim3(NGRAPH, 16), 128>>>();
    final_linear<<<NGRAPH, 320>>>(Wl, bl, out);
}